// round 3
// baseline (speedup 1.0000x reference)
#include <cuda_runtime.h>

#define NB 32
#define NC 512
#define NT 1024
#define SCALE_F 0.04419417382415922f  // 1/sqrt(512)

// Scratch (allocation-free rule: __device__ globals)
__device__ float d_q[NB * NC * NT];
__device__ float d_k[NB * NC * NT];
__device__ float d_v[NB * NC * NT];
__device__ float d_e[NB * NC * NC];

// ---------------------------------------------------------------------------
// Kernel 1: gated linear.  out[b,d,t] = g[b,d,t] * (sum_c x[b,c,t]*W[d,c] + bias[d])
// GEMM per batch: M = t (1024), N = d (512), K = c (512).
// A[t,c] = x[b,c,t]  (contiguous in t)  -> direct smem rows As[k][t]
// B[d,c] = W[d,c]    (contiguous in c)  -> transposed scatter Bs[k][d]
// Tile 128x128x16, 256 threads, 8x8 per thread.
// ---------------------------------------------------------------------------
__global__ __launch_bounds__(256, 2) void qkv_gemm(
    const float* __restrict__ x, const float* __restrict__ g,
    const float* __restrict__ W, const float* __restrict__ bias,
    float* __restrict__ out)
{
    __shared__ float As[16][128];   // [k][t]
    __shared__ float Bs[16][132];   // [k][d]  (padded vs bank conflicts)
    const int b = blockIdx.z;
    const int tBase = blockIdx.x * 128;
    const int dBase = blockIdx.y * 128;
    const int tid = threadIdx.x;
    const int aIdx = tid & 15;   // t-fragment selector
    const int bIdx = tid >> 4;   // d-fragment selector

    const float* xb = x + (size_t)b * NC * NT;

    float acc[8][8];
#pragma unroll
    for (int i = 0; i < 8; i++)
#pragma unroll
        for (int j = 0; j < 8; j++) acc[i][j] = 0.f;

    for (int kk = 0; kk < NC; kk += 16) {
        // A tile: 16 rows (k) x 128 (t), 512 float4 loads, 2 per thread
#pragma unroll
        for (int it = 0; it < 2; it++) {
            int idx  = tid + it * 256;
            int row  = idx >> 5;
            int col4 = idx & 31;
            float4 v4 = *(const float4*)&xb[(size_t)(kk + row) * NT + tBase + col4 * 4];
            *(float4*)&As[row][col4 * 4] = v4;
        }
        // B tile: W rows contiguous in k -> transpose into Bs[k][d]
#pragma unroll
        for (int it = 0; it < 2; it++) {
            int idx = tid + it * 256;
            int dd  = idx >> 2;
            int k4  = idx & 3;
            float4 v4 = *(const float4*)&W[(size_t)(dBase + dd) * NC + kk + k4 * 4];
            Bs[k4 * 4 + 0][dd] = v4.x;
            Bs[k4 * 4 + 1][dd] = v4.y;
            Bs[k4 * 4 + 2][dd] = v4.z;
            Bs[k4 * 4 + 3][dd] = v4.w;
        }
        __syncthreads();
#pragma unroll
        for (int k = 0; k < 16; k++) {
            float4 a0 = *(float4*)&As[k][aIdx * 4];
            float4 a1 = *(float4*)&As[k][64 + aIdx * 4];
            float4 b0 = *(float4*)&Bs[k][bIdx * 4];
            float4 b1 = *(float4*)&Bs[k][64 + bIdx * 4];
            float av[8] = {a0.x, a0.y, a0.z, a0.w, a1.x, a1.y, a1.z, a1.w};
            float bv[8] = {b0.x, b0.y, b0.z, b0.w, b1.x, b1.y, b1.z, b1.w};
#pragma unroll
            for (int i = 0; i < 8; i++)
#pragma unroll
                for (int j = 0; j < 8; j++) acc[i][j] += bv[i] * av[j];
        }
        __syncthreads();
    }

    // Epilogue: gate + bias, contiguous float4 stores along t
#pragma unroll
    for (int i = 0; i < 8; i++) {
        int dglob = dBase + ((i < 4) ? (bIdx * 4 + i) : (64 + bIdx * 4 + i - 4));
        float bb = bias[dglob];
        const float* grow = g + ((size_t)b * NC + dglob) * NT;
        float* orow = out + ((size_t)b * NC + dglob) * NT;
#pragma unroll
        for (int jj = 0; jj < 2; jj++) {
            int t0 = tBase + jj * 64 + aIdx * 4;
            float4 g4 = *(const float4*)&grow[t0];
            float4 o4;
            o4.x = g4.x * (acc[i][jj * 4 + 0] + bb);
            o4.y = g4.y * (acc[i][jj * 4 + 1] + bb);
            o4.z = g4.z * (acc[i][jj * 4 + 2] + bb);
            o4.w = g4.w * (acc[i][jj * 4 + 3] + bb);
            *(float4*)&orow[t0] = o4;
        }
    }
}

// ---------------------------------------------------------------------------
// Kernel 2: energy[b,c,d] = sum_t q[b,c,t]*k[b,d,t]   (NT GEMM, K = t = 1024)
// Both operands K-contiguous -> both transposed scatters into smem.
// ---------------------------------------------------------------------------
__global__ __launch_bounds__(256, 2) void energy_gemm(
    const float* __restrict__ q, const float* __restrict__ kmat,
    float* __restrict__ e)
{
    __shared__ float As[16][132];  // [t-k][c]
    __shared__ float Bs[16][132];  // [t-k][d]
    const int b = blockIdx.z;
    const int cBase = blockIdx.y * 128;
    const int dBase = blockIdx.x * 128;
    const int tid = threadIdx.x;
    const int aIdx = tid & 15;   // c fragment
    const int bIdx = tid >> 4;   // d fragment

    const float* qb = q + (size_t)b * NC * NT;
    const float* kb = kmat + (size_t)b * NC * NT;

    float acc[8][8];
#pragma unroll
    for (int i = 0; i < 8; i++)
#pragma unroll
        for (int j = 0; j < 8; j++) acc[i][j] = 0.f;

    for (int kk = 0; kk < NT; kk += 16) {
#pragma unroll
        for (int it = 0; it < 2; it++) {
            int idx = tid + it * 256;
            int m = idx >> 2;
            int k4 = idx & 3;
            float4 va = *(const float4*)&qb[(size_t)(cBase + m) * NT + kk + k4 * 4];
            As[k4 * 4 + 0][m] = va.x;
            As[k4 * 4 + 1][m] = va.y;
            As[k4 * 4 + 2][m] = va.z;
            As[k4 * 4 + 3][m] = va.w;
            float4 vb = *(const float4*)&kb[(size_t)(dBase + m) * NT + kk + k4 * 4];
            Bs[k4 * 4 + 0][m] = vb.x;
            Bs[k4 * 4 + 1][m] = vb.y;
            Bs[k4 * 4 + 2][m] = vb.z;
            Bs[k4 * 4 + 3][m] = vb.w;
        }
        __syncthreads();
#pragma unroll
        for (int k = 0; k < 16; k++) {
            float4 a0 = *(float4*)&As[k][aIdx * 4];
            float4 a1 = *(float4*)&As[k][64 + aIdx * 4];
            float4 b0 = *(float4*)&Bs[k][bIdx * 4];
            float4 b1 = *(float4*)&Bs[k][64 + bIdx * 4];
            float av[8] = {a0.x, a0.y, a0.z, a0.w, a1.x, a1.y, a1.z, a1.w};
            float bv[8] = {b0.x, b0.y, b0.z, b0.w, b1.x, b1.y, b1.z, b1.w};
#pragma unroll
            for (int i = 0; i < 8; i++)
#pragma unroll
                for (int j = 0; j < 8; j++) acc[i][j] += bv[i] * av[j];
        }
        __syncthreads();
    }

    // store: e contiguous in d; for fixed c fragment, d fragments are 4-contiguous
#pragma unroll
    for (int j = 0; j < 8; j++) {
        int cglob = cBase + ((j < 4) ? (aIdx * 4 + j) : (64 + aIdx * 4 + j - 4));
        float* erow = e + ((size_t)b * NC + cglob) * NC;
        float4 v0 = make_float4(acc[0][j], acc[1][j], acc[2][j], acc[3][j]);
        float4 v1 = make_float4(acc[4][j], acc[5][j], acc[6][j], acc[7][j]);
        *(float4*)&erow[dBase + bIdx * 4] = v0;
        *(float4*)&erow[dBase + 64 + bIdx * 4] = v1;
    }
}

// ---------------------------------------------------------------------------
// Kernel 3: in-place softmax over rows of e (512 cols), with SCALE applied.
// One block (128 threads) per row, 4 elements per thread.
// ---------------------------------------------------------------------------
__global__ __launch_bounds__(128) void softmax_kernel(float* __restrict__ e)
{
    const size_t row = blockIdx.x;
    float* p = e + row * NC;
    const int tid = threadIdx.x;
    const int lane = tid & 31;
    const int warp = tid >> 5;
    __shared__ float smax[4];
    __shared__ float ssum[4];

    float4 v = *(float4*)&p[tid * 4];
    float sx = v.x * SCALE_F, sy = v.y * SCALE_F, sz = v.z * SCALE_F, sw = v.w * SCALE_F;

    float m = fmaxf(fmaxf(sx, sy), fmaxf(sz, sw));
#pragma unroll
    for (int o = 16; o > 0; o >>= 1) m = fmaxf(m, __shfl_xor_sync(0xffffffffu, m, o));
    if (lane == 0) smax[warp] = m;
    __syncthreads();
    m = fmaxf(fmaxf(smax[0], smax[1]), fmaxf(smax[2], smax[3]));

    float e0 = __expf(sx - m);
    float e1 = __expf(sy - m);
    float e2 = __expf(sz - m);
    float e3 = __expf(sw - m);
    float s = e0 + e1 + e2 + e3;
#pragma unroll
    for (int o = 16; o > 0; o >>= 1) s += __shfl_xor_sync(0xffffffffu, s, o);
    if (lane == 0) ssum[warp] = s;
    __syncthreads();
    s = ssum[0] + ssum[1] + ssum[2] + ssum[3];
    float inv = 1.0f / s;

    float4 o4 = make_float4(e0 * inv, e1 * inv, e2 * inv, e3 * inv);
    *(float4*)&p[tid * 4] = o4;
}

// ---------------------------------------------------------------------------
// Kernel 4: out[b,c,t] = sum_d attn[b,c,d] * v[b,d,t]   (NN GEMM, K = d = 512)
// A = attn (contiguous in d=K -> transpose), B = v (contiguous in t=N -> direct)
// ---------------------------------------------------------------------------
__global__ __launch_bounds__(256, 2) void out_gemm(
    const float* __restrict__ attn, const float* __restrict__ v,
    float* __restrict__ out)
{
    __shared__ float As[16][132];  // [d-k][c]
    __shared__ float Bs[16][128];  // [d-k][t]
    const int b = blockIdx.z;
    const int cBase = blockIdx.y * 128;
    const int tBase = blockIdx.x * 128;
    const int tid = threadIdx.x;
    const int aIdx = tid & 15;   // c fragment
    const int bIdx = tid >> 4;   // t fragment

    const float* ab = attn + (size_t)b * NC * NC;
    const float* vb = v + (size_t)b * NC * NT;

    float acc[8][8];
#pragma unroll
    for (int i = 0; i < 8; i++)
#pragma unroll
        for (int j = 0; j < 8; j++) acc[i][j] = 0.f;

    for (int kk = 0; kk < NC; kk += 16) {
#pragma unroll
        for (int it = 0; it < 2; it++) {
            int idx = tid + it * 256;
            int m = idx >> 2;
            int k4 = idx & 3;
            float4 va = *(const float4*)&ab[(size_t)(cBase + m) * NC + kk + k4 * 4];
            As[k4 * 4 + 0][m] = va.x;
            As[k4 * 4 + 1][m] = va.y;
            As[k4 * 4 + 2][m] = va.z;
            As[k4 * 4 + 3][m] = va.w;
        }
#pragma unroll
        for (int it = 0; it < 2; it++) {
            int idx  = tid + it * 256;
            int row  = idx >> 5;
            int col4 = idx & 31;
            float4 v4 = *(const float4*)&vb[(size_t)(kk + row) * NT + tBase + col4 * 4];
            *(float4*)&Bs[row][col4 * 4] = v4;
        }
        __syncthreads();
#pragma unroll
        for (int k = 0; k < 16; k++) {
            float4 a0 = *(float4*)&As[k][aIdx * 4];
            float4 a1 = *(float4*)&As[k][64 + aIdx * 4];
            float4 b0 = *(float4*)&Bs[k][bIdx * 4];
            float4 b1 = *(float4*)&Bs[k][64 + bIdx * 4];
            float av[8] = {a0.x, a0.y, a0.z, a0.w, a1.x, a1.y, a1.z, a1.w};
            float bv[8] = {b0.x, b0.y, b0.z, b0.w, b1.x, b1.y, b1.z, b1.w};
#pragma unroll
            for (int i = 0; i < 8; i++)
#pragma unroll
                for (int j = 0; j < 8; j++) acc[i][j] += bv[i] * av[j];
        }
        __syncthreads();
    }

    // out contiguous in t; t fragments 4-contiguous
#pragma unroll
    for (int j = 0; j < 8; j++) {
        int cglob = cBase + ((j < 4) ? (aIdx * 4 + j) : (64 + aIdx * 4 + j - 4));
        float* orow = out + ((size_t)b * NC + cglob) * NT;
        float4 v0 = make_float4(acc[0][j], acc[1][j], acc[2][j], acc[3][j]);
        float4 v1 = make_float4(acc[4][j], acc[5][j], acc[6][j], acc[7][j]);
        *(float4*)&orow[tBase + bIdx * 4] = v0;
        *(float4*)&orow[tBase + 64 + bIdx * 4] = v1;
    }
}

// ---------------------------------------------------------------------------
extern "C" void kernel_launch(void* const* d_in, const int* in_sizes, int n_in,
                              void* d_out, int out_size)
{
    const float* x  = (const float*)d_in[0];
    const float* gq = (const float*)d_in[1];
    const float* gk = (const float*)d_in[2];
    const float* gv = (const float*)d_in[3];
    const float* Wq = (const float*)d_in[4];
    const float* bq = (const float*)d_in[5];
    const float* Wk = (const float*)d_in[6];
    const float* bk = (const float*)d_in[7];
    const float* Wv = (const float*)d_in[8];
    const float* bv = (const float*)d_in[9];
    float* out = (float*)d_out;

    float *q, *k, *v, *e;
    cudaGetSymbolAddress((void**)&q, d_q);
    cudaGetSymbolAddress((void**)&k, d_k);
    cudaGetSymbolAddress((void**)&v, d_v);
    cudaGetSymbolAddress((void**)&e, d_e);

    dim3 gQKV(NT / 128, NC / 128, NB);   // (8, 4, 32)
    qkv_gemm<<<gQKV, 256>>>(x, gq, Wq, bq, q);
    qkv_gemm<<<gQKV, 256>>>(x, gk, Wk, bk, k);
    qkv_gemm<<<gQKV, 256>>>(x, gv, Wv, bv, v);

    dim3 gE(NC / 128, NC / 128, NB);     // (4, 4, 32)
    energy_gemm<<<gE, 256>>>(q, k, e);

    softmax_kernel<<<NB * NC, 128>>>(e);

    dim3 gO(NT / 128, NC / 128, NB);     // (8, 4, 32)
    out_gemm<<<gO, 256>>>(e, v, out);
}

// round 4
// speedup vs baseline: 1.6221x; 1.6221x over previous
#include <cuda_runtime.h>

#define NB 32
#define NC 512
#define NT 1024
#define SCALE_F 0.04419417382415922f  // 1/sqrt(512)

// Scratch (allocation-free rule: __device__ globals)
__device__ float d_q[NB * NC * NT];
__device__ float d_k[NB * NC * NT];
__device__ float d_v[NB * NC * NT];
__device__ float d_e[NB * NC * NC];

// ---------------------------------------------------------------------------
// Kernel 1: gated linear.  out[b,d,t] = g[b,d,t] * (sum_c x[b,c,t]*W[d,c] + bias[d])
// GEMM per batch: M = t (1024), N = d (512), K = c (512).
// A[t,c] = x[b,c,t]  (contiguous in t)  -> direct smem rows As[k][t]
// B[d,c] = W[d,c]    (contiguous in c)  -> transposed scatter Bs[k][d]
// Tile 128x128x16, 256 threads, 8x8 per thread.
// ---------------------------------------------------------------------------
__global__ __launch_bounds__(256, 2) void qkv_gemm(
    const float* __restrict__ x, const float* __restrict__ g,
    const float* __restrict__ W, const float* __restrict__ bias,
    float* __restrict__ out)
{
    __shared__ float As[16][128];   // [k][t]
    __shared__ float Bs[16][132];   // [k][d]  (padded vs bank conflicts)
    const int b = blockIdx.z;
    const int tBase = blockIdx.x * 128;
    const int dBase = blockIdx.y * 128;
    const int tid = threadIdx.x;
    const int aIdx = tid & 15;   // t-fragment selector
    const int bIdx = tid >> 4;   // d-fragment selector

    const float* xb = x + (size_t)b * NC * NT;

    float acc[8][8];
#pragma unroll
    for (int i = 0; i < 8; i++)
#pragma unroll
        for (int j = 0; j < 8; j++) acc[i][j] = 0.f;

    for (int kk = 0; kk < NC; kk += 16) {
        // A tile: 16 rows (k) x 128 (t), 512 float4 loads, 2 per thread
#pragma unroll
        for (int it = 0; it < 2; it++) {
            int idx  = tid + it * 256;
            int row  = idx >> 5;
            int col4 = idx & 31;
            float4 v4 = *(const float4*)&xb[(size_t)(kk + row) * NT + tBase + col4 * 4];
            *(float4*)&As[row][col4 * 4] = v4;
        }
        // B tile: W rows contiguous in k -> transpose into Bs[k][d]
#pragma unroll
        for (int it = 0; it < 2; it++) {
            int idx = tid + it * 256;
            int dd  = idx >> 2;
            int k4  = idx & 3;
            float4 v4 = *(const float4*)&W[(size_t)(dBase + dd) * NC + kk + k4 * 4];
            Bs[k4 * 4 + 0][dd] = v4.x;
            Bs[k4 * 4 + 1][dd] = v4.y;
            Bs[k4 * 4 + 2][dd] = v4.z;
            Bs[k4 * 4 + 3][dd] = v4.w;
        }
        __syncthreads();
#pragma unroll
        for (int k = 0; k < 16; k++) {
            float4 a0 = *(float4*)&As[k][aIdx * 4];
            float4 a1 = *(float4*)&As[k][64 + aIdx * 4];
            float4 b0 = *(float4*)&Bs[k][bIdx * 4];
            float4 b1 = *(float4*)&Bs[k][64 + bIdx * 4];
            float av[8] = {a0.x, a0.y, a0.z, a0.w, a1.x, a1.y, a1.z, a1.w};
            float bv[8] = {b0.x, b0.y, b0.z, b0.w, b1.x, b1.y, b1.z, b1.w};
#pragma unroll
            for (int i = 0; i < 8; i++)
#pragma unroll
                for (int j = 0; j < 8; j++) acc[i][j] += bv[i] * av[j];
        }
        __syncthreads();
    }

    // Epilogue: gate + bias, contiguous float4 stores along t
#pragma unroll
    for (int i = 0; i < 8; i++) {
        int dglob = dBase + ((i < 4) ? (bIdx * 4 + i) : (64 + bIdx * 4 + i - 4));
        float bb = bias[dglob];
        const float* grow = g + ((size_t)b * NC + dglob) * NT;
        float* orow = out + ((size_t)b * NC + dglob) * NT;
#pragma unroll
        for (int jj = 0; jj < 2; jj++) {
            int t0 = tBase + jj * 64 + aIdx * 4;
            float4 g4 = *(const float4*)&grow[t0];
            float4 o4;
            o4.x = g4.x * (acc[i][jj * 4 + 0] + bb);
            o4.y = g4.y * (acc[i][jj * 4 + 1] + bb);
            o4.z = g4.z * (acc[i][jj * 4 + 2] + bb);
            o4.w = g4.w * (acc[i][jj * 4 + 3] + bb);
            *(float4*)&orow[t0] = o4;
        }
    }
}

// ---------------------------------------------------------------------------
// Kernel 2: energy[b,c,d] = sum_t q[b,c,t]*k[b,d,t]   (NT GEMM, K = t = 1024)
// Both operands K-contiguous -> both transposed scatters into smem.
// ---------------------------------------------------------------------------
__global__ __launch_bounds__(256, 2) void energy_gemm(
    const float* __restrict__ q, const float* __restrict__ kmat,
    float* __restrict__ e)
{
    __shared__ float As[16][132];  // [t-k][c]
    __shared__ float Bs[16][132];  // [t-k][d]
    const int b = blockIdx.z;
    const int cBase = blockIdx.y * 128;
    const int dBase = blockIdx.x * 128;
    const int tid = threadIdx.x;
    const int aIdx = tid & 15;   // c fragment
    const int bIdx = tid >> 4;   // d fragment

    const float* qb = q + (size_t)b * NC * NT;
    const float* kb = kmat + (size_t)b * NC * NT;

    float acc[8][8];
#pragma unroll
    for (int i = 0; i < 8; i++)
#pragma unroll
        for (int j = 0; j < 8; j++) acc[i][j] = 0.f;

    for (int kk = 0; kk < NT; kk += 16) {
#pragma unroll
        for (int it = 0; it < 2; it++) {
            int idx = tid + it * 256;
            int m = idx >> 2;
            int k4 = idx & 3;
            float4 va = *(const float4*)&qb[(size_t)(cBase + m) * NT + kk + k4 * 4];
            As[k4 * 4 + 0][m] = va.x;
            As[k4 * 4 + 1][m] = va.y;
            As[k4 * 4 + 2][m] = va.z;
            As[k4 * 4 + 3][m] = va.w;
            float4 vb = *(const float4*)&kb[(size_t)(dBase + m) * NT + kk + k4 * 4];
            Bs[k4 * 4 + 0][m] = vb.x;
            Bs[k4 * 4 + 1][m] = vb.y;
            Bs[k4 * 4 + 2][m] = vb.z;
            Bs[k4 * 4 + 3][m] = vb.w;
        }
        __syncthreads();
#pragma unroll
        for (int k = 0; k < 16; k++) {
            float4 a0 = *(float4*)&As[k][aIdx * 4];
            float4 a1 = *(float4*)&As[k][64 + aIdx * 4];
            float4 b0 = *(float4*)&Bs[k][bIdx * 4];
            float4 b1 = *(float4*)&Bs[k][64 + bIdx * 4];
            float av[8] = {a0.x, a0.y, a0.z, a0.w, a1.x, a1.y, a1.z, a1.w};
            float bv[8] = {b0.x, b0.y, b0.z, b0.w, b1.x, b1.y, b1.z, b1.w};
#pragma unroll
            for (int i = 0; i < 8; i++)
#pragma unroll
                for (int j = 0; j < 8; j++) acc[i][j] += bv[i] * av[j];
        }
        __syncthreads();
    }

    // store: e contiguous in d; for fixed c fragment, d fragments are 4-contiguous
#pragma unroll
    for (int j = 0; j < 8; j++) {
        int cglob = cBase + ((j < 4) ? (aIdx * 4 + j) : (64 + aIdx * 4 + j - 4));
        float* erow = e + ((size_t)b * NC + cglob) * NC;
        float4 v0 = make_float4(acc[0][j], acc[1][j], acc[2][j], acc[3][j]);
        float4 v1 = make_float4(acc[4][j], acc[5][j], acc[6][j], acc[7][j]);
        *(float4*)&erow[dBase + bIdx * 4] = v0;
        *(float4*)&erow[dBase + 64 + bIdx * 4] = v1;
    }
}

// ---------------------------------------------------------------------------
// Kernel 3: in-place softmax over rows of e (512 cols), with SCALE applied.
// One block (128 threads) per row, 4 elements per thread.
// ---------------------------------------------------------------------------
__global__ __launch_bounds__(128) void softmax_kernel(float* __restrict__ e)
{
    const size_t row = blockIdx.x;
    float* p = e + row * NC;
    const int tid = threadIdx.x;
    const int lane = tid & 31;
    const int warp = tid >> 5;
    __shared__ float smax[4];
    __shared__ float ssum[4];

    float4 v = *(float4*)&p[tid * 4];
    float sx = v.x * SCALE_F, sy = v.y * SCALE_F, sz = v.z * SCALE_F, sw = v.w * SCALE_F;

    float m = fmaxf(fmaxf(sx, sy), fmaxf(sz, sw));
#pragma unroll
    for (int o = 16; o > 0; o >>= 1) m = fmaxf(m, __shfl_xor_sync(0xffffffffu, m, o));
    if (lane == 0) smax[warp] = m;
    __syncthreads();
    m = fmaxf(fmaxf(smax[0], smax[1]), fmaxf(smax[2], smax[3]));

    float e0 = __expf(sx - m);
    float e1 = __expf(sy - m);
    float e2 = __expf(sz - m);
    float e3 = __expf(sw - m);
    float s = e0 + e1 + e2 + e3;
#pragma unroll
    for (int o = 16; o > 0; o >>= 1) s += __shfl_xor_sync(0xffffffffu, s, o);
    if (lane == 0) ssum[warp] = s;
    __syncthreads();
    s = ssum[0] + ssum[1] + ssum[2] + ssum[3];
    float inv = 1.0f / s;

    float4 o4 = make_float4(e0 * inv, e1 * inv, e2 * inv, e3 * inv);
    *(float4*)&p[tid * 4] = o4;
}

// ---------------------------------------------------------------------------
// Kernel 4: out[b,c,t] = sum_d attn[b,c,d] * v[b,d,t]   (NN GEMM, K = d = 512)
// A = attn (contiguous in d=K -> transpose), B = v (contiguous in t=N -> direct)
// ---------------------------------------------------------------------------
__global__ __launch_bounds__(256, 2) void out_gemm(
    const float* __restrict__ attn, const float* __restrict__ v,
    float* __restrict__ out)
{
    __shared__ float As[16][132];  // [d-k][c]
    __shared__ float Bs[16][128];  // [d-k][t]
    const int b = blockIdx.z;
    const int cBase = blockIdx.y * 128;
    const int tBase = blockIdx.x * 128;
    const int tid = threadIdx.x;
    const int aIdx = tid & 15;   // c fragment
    const int bIdx = tid >> 4;   // t fragment

    const float* ab = attn + (size_t)b * NC * NC;
    const float* vb = v + (size_t)b * NC * NT;

    float acc[8][8];
#pragma unroll
    for (int i = 0; i < 8; i++)
#pragma unroll
        for (int j = 0; j < 8; j++) acc[i][j] = 0.f;

    for (int kk = 0; kk < NC; kk += 16) {
#pragma unroll
        for (int it = 0; it < 2; it++) {
            int idx = tid + it * 256;
            int m = idx >> 2;
            int k4 = idx & 3;
            float4 va = *(const float4*)&ab[(size_t)(cBase + m) * NC + kk + k4 * 4];
            As[k4 * 4 + 0][m] = va.x;
            As[k4 * 4 + 1][m] = va.y;
            As[k4 * 4 + 2][m] = va.z;
            As[k4 * 4 + 3][m] = va.w;
        }
#pragma unroll
        for (int it = 0; it < 2; it++) {
            int idx  = tid + it * 256;
            int row  = idx >> 5;
            int col4 = idx & 31;
            float4 v4 = *(const float4*)&vb[(size_t)(kk + row) * NT + tBase + col4 * 4];
            *(float4*)&Bs[row][col4 * 4] = v4;
        }
        __syncthreads();
#pragma unroll
        for (int k = 0; k < 16; k++) {
            float4 a0 = *(float4*)&As[k][aIdx * 4];
            float4 a1 = *(float4*)&As[k][64 + aIdx * 4];
            float4 b0 = *(float4*)&Bs[k][bIdx * 4];
            float4 b1 = *(float4*)&Bs[k][64 + bIdx * 4];
            float av[8] = {a0.x, a0.y, a0.z, a0.w, a1.x, a1.y, a1.z, a1.w};
            float bv[8] = {b0.x, b0.y, b0.z, b0.w, b1.x, b1.y, b1.z, b1.w};
#pragma unroll
            for (int i = 0; i < 8; i++)
#pragma unroll
                for (int j = 0; j < 8; j++) acc[i][j] += bv[i] * av[j];
        }
        __syncthreads();
    }

    // out contiguous in t; t fragments 4-contiguous
#pragma unroll
    for (int j = 0; j < 8; j++) {
        int cglob = cBase + ((j < 4) ? (aIdx * 4 + j) : (64 + aIdx * 4 + j - 4));
        float* orow = out + ((size_t)b * NC + cglob) * NT;
        float4 v0 = make_float4(acc[0][j], acc[1][j], acc[2][j], acc[3][j]);
        float4 v1 = make_float4(acc[4][j], acc[5][j], acc[6][j], acc[7][j]);
        *(float4*)&orow[tBase + bIdx * 4] = v0;
        *(float4*)&orow[tBase + 64 + bIdx * 4] = v1;
    }
}

// ---------------------------------------------------------------------------
extern "C" void kernel_launch(void* const* d_in, const int* in_sizes, int n_in,
                              void* d_out, int out_size)
{
    const float* x  = (const float*)d_in[0];
    const float* gq = (const float*)d_in[1];
    const float* gk = (const float*)d_in[2];
    const float* gv = (const float*)d_in[3];
    const float* Wq = (const float*)d_in[4];
    const float* bq = (const float*)d_in[5];
    const float* Wk = (const float*)d_in[6];
    const float* bk = (const float*)d_in[7];
    const float* Wv = (const float*)d_in[8];
    const float* bv = (const float*)d_in[9];
    float* out = (float*)d_out;

    float *q, *k, *v, *e;
    cudaGetSymbolAddress((void**)&q, d_q);
    cudaGetSymbolAddress((void**)&k, d_k);
    cudaGetSymbolAddress((void**)&v, d_v);
    cudaGetSymbolAddress((void**)&e, d_e);

    dim3 gQKV(NT / 128, NC / 128, NB);   // (8, 4, 32)
    qkv_gemm<<<gQKV, 256>>>(x, gq, Wq, bq, q);
    qkv_gemm<<<gQKV, 256>>>(x, gk, Wk, bk, k);
    qkv_gemm<<<gQKV, 256>>>(x, gv, Wv, bv, v);

    dim3 gE(NC / 128, NC / 128, NB);     // (4, 4, 32)
    energy_gemm<<<gE, 256>>>(q, k, e);

    softmax_kernel<<<NB * NC, 128>>>(e);

    dim3 gO(NT / 128, NC / 128, NB);     // (8, 4, 32)
    out_gemm<<<gO, 256>>>(e, v, out);
}

// round 6
// speedup vs baseline: 3.1210x; 1.9241x over previous
#include <cuda_runtime.h>
#include <cuda_bf16.h>
#include <cstdint>

#define NB 32
#define NC 512
#define NT 1024
#define SCALE_F 0.04419417382415922f  // 1/sqrt(512)

#define TROW 144                       // padded smem row: 64 bf16 + 8 pad = 144B (16B-mult, conflict-free)
#define TSZ  (128 * TROW)              // 18432 B per tile
#define SMEM_DYN (2 * 4 * TSZ)         // 2 stages x 4 tiles = 147456 B

// ---------------------------------------------------------------------------
// Scratch (__device__ globals: allocation-free rule)
// ---------------------------------------------------------------------------
__device__ __align__(256) __nv_bfloat16 g_xThi[(size_t)NB * NT * NC];
__device__ __align__(256) __nv_bfloat16 g_xTlo[(size_t)NB * NT * NC];
__device__ __align__(256) __nv_bfloat16 g_qhi [(size_t)NB * NC * NT];
__device__ __align__(256) __nv_bfloat16 g_qlo [(size_t)NB * NC * NT];
__device__ __align__(256) __nv_bfloat16 g_khi [(size_t)NB * NC * NT];
__device__ __align__(256) __nv_bfloat16 g_klo [(size_t)NB * NC * NT];
__device__ __align__(256) __nv_bfloat16 g_vThi[(size_t)NB * NT * NC];
__device__ __align__(256) __nv_bfloat16 g_vTlo[(size_t)NB * NT * NC];
__device__ __align__(256) __nv_bfloat16 g_ahi [(size_t)NB * NC * NC];
__device__ __align__(256) __nv_bfloat16 g_alo [(size_t)NB * NC * NC];
__device__ __align__(256) __nv_bfloat16 g_Whi [3 * (size_t)NC * NC];
__device__ __align__(256) __nv_bfloat16 g_Wlo [3 * (size_t)NC * NC];
__device__ __align__(256) float         g_e   [(size_t)NB * NC * NC];

// ---------------------------------------------------------------------------
// Baseline-ISA helpers (no 'a'-suffix features: cp.async / ldmatrix / mma.sync)
// ---------------------------------------------------------------------------
__device__ __forceinline__ uint32_t cvta_shared_u32(const void* p) {
    uint32_t a;
    asm("{ .reg .u64 t; cvta.to.shared.u64 t, %1; cvt.u32.u64 %0, t; }" : "=r"(a) : "l"(p));
    return a;
}
__device__ __forceinline__ void cpasync16(uint32_t s, const void* g) {
    asm volatile("cp.async.cg.shared.global [%0], [%1], 16;" :: "r"(s), "l"(g));
}
#define CP_COMMIT() asm volatile("cp.async.commit_group;")
#define CP_WAIT1()  asm volatile("cp.async.wait_group 1;")
#define CP_WAIT0()  asm volatile("cp.async.wait_group 0;")

__device__ __forceinline__ void ldm_x4(uint32_t* r, uint32_t addr) {
    asm volatile("ldmatrix.sync.aligned.m8n8.x4.shared.b16 {%0,%1,%2,%3}, [%4];"
                 : "=r"(r[0]), "=r"(r[1]), "=r"(r[2]), "=r"(r[3]) : "r"(addr));
}
__device__ __forceinline__ void mma_bf16(float* c, const uint32_t* a, uint32_t b0, uint32_t b1) {
    asm volatile("mma.sync.aligned.m16n8k16.row.col.f32.bf16.bf16.f32 "
                 "{%0,%1,%2,%3}, {%4,%5,%6,%7}, {%8,%9}, {%0,%1,%2,%3};"
                 : "+f"(c[0]), "+f"(c[1]), "+f"(c[2]), "+f"(c[3])
                 : "r"(a[0]), "r"(a[1]), "r"(a[2]), "r"(a[3]), "r"(b0), "r"(b1));
}

__device__ __forceinline__ uint32_t pack_bf2(__nv_bfloat16 a, __nv_bfloat16 b) {
    __nv_bfloat162 t = __halves2bfloat162(a, b);
    return *reinterpret_cast<uint32_t*>(&t);
}
__device__ __forceinline__ void split2(float v, __nv_bfloat16& h, __nv_bfloat16& l) {
    h = __float2bfloat16(v);
    l = __float2bfloat16(v - __bfloat162float(h));
}

// ---------------------------------------------------------------------------
// Prep kernels
// ---------------------------------------------------------------------------
__global__ __launch_bounds__(256) void transpose_split(
    const float* __restrict__ x,
    __nv_bfloat16* __restrict__ xHi, __nv_bfloat16* __restrict__ xLo)
{
    __shared__ float tile[32][33];
    const int b = blockIdx.z, c0 = blockIdx.y * 32, t0 = blockIdx.x * 32;
    const int tx = threadIdx.x, ty = threadIdx.y;  // (32, 8)
#pragma unroll
    for (int j = 0; j < 4; ++j)
        tile[ty + j * 8][tx] = x[((size_t)b * NC + c0 + ty + j * 8) * NT + t0 + tx];
    __syncthreads();
#pragma unroll
    for (int j = 0; j < 4; ++j) {
        int t = t0 + ty + j * 8, cc = c0 + tx;
        float v = tile[tx][ty + j * 8];
        __nv_bfloat16 h, l; split2(v, h, l);
        size_t o = ((size_t)b * NT + t) * NC + cc;
        xHi[o] = h; xLo[o] = l;
    }
}

__global__ __launch_bounds__(256) void split_kernel(
    const float* __restrict__ src,
    __nv_bfloat16* __restrict__ hi, __nv_bfloat16* __restrict__ lo)
{
    size_t i = ((size_t)blockIdx.x * 256 + threadIdx.x) * 4;
    float4 v = *(const float4*)&src[i];
    __nv_bfloat16 h0, l0, h1, l1, h2, l2, h3, l3;
    split2(v.x, h0, l0); split2(v.y, h1, l1); split2(v.z, h2, l2); split2(v.w, h3, l3);
    *(uint2*)(hi + i) = make_uint2(pack_bf2(h0, h1), pack_bf2(h2, h3));
    *(uint2*)(lo + i) = make_uint2(pack_bf2(l0, l1), pack_bf2(l2, l3));
}

// ---------------------------------------------------------------------------
// Unified split-3 bf16 tensor-core GEMM:  D[m,n] = sum_k A[m,k]*B[n,k]
// Both operands K-contiguous planes (hi/lo). 128x128 tile, K-chunk 64,
// 2-stage cp.async pipeline. 8 warps (2x4), warp tile 64x32, m16n8k16.
// EPI 0: q/k epilogue -> gate*(D+bias) split planes [b,m,n] (m=d rows, n=t)
// EPI 1: v epilogue   -> gated, transposed split planes vT [b,n,m]
// EPI 2: raw fp32 out -> fOut[b*oBatch + (mBase+r)*oStr + nBase+c]
// ---------------------------------------------------------------------------
template <int EPI>
__global__ __launch_bounds__(256, 1) void gemm_tc(
    const __nv_bfloat16* __restrict__ aHi, const __nv_bfloat16* __restrict__ aLo,
    const __nv_bfloat16* __restrict__ bHi, const __nv_bfloat16* __restrict__ bLo,
    int aStr, int bStr, size_t aBatch, size_t bBatch, int nCh,
    const float* __restrict__ g, const float* __restrict__ bias,
    float* __restrict__ fOut, int oStr, size_t oBatch,
    __nv_bfloat16* __restrict__ oHi, __nv_bfloat16* __restrict__ oLo)
{
    extern __shared__ char sm[];
    const uint32_t smb = cvta_shared_u32(sm);
    const int tid = threadIdx.x, lane = tid & 31, wid = tid >> 5;
    const int wm = wid >> 2, wn = wid & 3;
    const int b = blockIdx.z, mBase = blockIdx.y * 128, nBase = blockIdx.x * 128;

    const __nv_bfloat16* aPH = aHi + (size_t)b * aBatch + (size_t)mBase * aStr;
    const __nv_bfloat16* aPL = aLo + (size_t)b * aBatch + (size_t)mBase * aStr;
    const __nv_bfloat16* bPH = bHi + (size_t)b * bBatch + (size_t)nBase * bStr;
    const __nv_bfloat16* bPL = bLo + (size_t)b * bBatch + (size_t)nBase * bStr;

    float acc[4][4][4];
#pragma unroll
    for (int i = 0; i < 4; i++)
#pragma unroll
        for (int j = 0; j < 4; j++)
#pragma unroll
            for (int p = 0; p < 4; p++) acc[i][j][p] = 0.f;

    const int r8 = tid >> 3, u8 = tid & 7;  // loader: 32 rows x 8 units per pass

    // ---- load chunk c into stage s
    auto load_chunk = [&](int c, int s) {
        const int kk = c * 64;
        const __nv_bfloat16* srcs[4] = { aPH + kk, aPL + kk, bPH + kk, bPL + kk };
        const int strs[4] = { aStr, aStr, bStr, bStr };
#pragma unroll
        for (int t = 0; t < 4; ++t) {
            uint32_t dst = smb + (uint32_t)(s * 4 + t) * TSZ;
            const __nv_bfloat16* sp = srcs[t];
            const int st = strs[t];
#pragma unroll
            for (int it = 0; it < 4; ++it) {
                int r = r8 + it * 32;
                cpasync16(dst + r * TROW + u8 * 16, sp + (size_t)r * st + u8 * 8);
            }
        }
    };

    // ---- compute one chunk from stage s
    auto compute_chunk = [&](int s) {
        const uint32_t tA0 = smb + (uint32_t)(s * 4 + 0) * TSZ;
        const uint32_t tA1 = smb + (uint32_t)(s * 4 + 1) * TSZ;
        const uint32_t tB0 = smb + (uint32_t)(s * 4 + 2) * TSZ;
        const uint32_t tB1 = smb + (uint32_t)(s * 4 + 3) * TSZ;
        const int aRow = wm * 64 + (lane & 15);
        const int aKo  = (lane >> 4) * 16;
        const int bRow = wn * 32 + (lane & 7) + ((lane >> 4) << 3);
        const int bKo  = ((lane >> 3) & 1) * 16;
#pragma unroll
        for (int ks = 0; ks < 4; ++ks) {
            uint32_t aF[2][4][4];
            uint32_t bF[2][2][4];
#pragma unroll
            for (int mi = 0; mi < 4; ++mi) {
                uint32_t off = (uint32_t)((aRow + mi * 16) * TROW + ks * 32 + aKo);
                ldm_x4(aF[0][mi], tA0 + off);
                ldm_x4(aF[1][mi], tA1 + off);
            }
#pragma unroll
            for (int jj = 0; jj < 2; ++jj) {
                uint32_t off = (uint32_t)((bRow + jj * 16) * TROW + ks * 32 + bKo);
                ldm_x4(bF[0][jj], tB0 + off);
                ldm_x4(bF[1][jj], tB1 + off);
            }
#pragma unroll
            for (int mi = 0; mi < 4; ++mi)
#pragma unroll
                for (int nj = 0; nj < 4; ++nj) {
                    const int jj = nj >> 1, p = (nj & 1) * 2;
                    mma_bf16(acc[mi][nj], aF[0][mi], bF[0][jj][p], bF[0][jj][p + 1]); // hi*hi
                    mma_bf16(acc[mi][nj], aF[0][mi], bF[1][jj][p], bF[1][jj][p + 1]); // hi*lo
                    mma_bf16(acc[mi][nj], aF[1][mi], bF[0][jj][p], bF[0][jj][p + 1]); // lo*hi
                }
        }
    };

    load_chunk(0, 0);
    CP_COMMIT();
    for (int c = 0; c < nCh; ++c) {
        if (c + 1 < nCh) {
            load_chunk(c + 1, (c + 1) & 1);
            CP_COMMIT();
            CP_WAIT1();
        } else {
            CP_WAIT0();
        }
        __syncthreads();
        compute_chunk(c & 1);
        __syncthreads();
    }

    // ---- stage accumulators to smem (reuse tile memory)
    float* stg = (float*)sm;  // [128][132]
#pragma unroll
    for (int mi = 0; mi < 4; ++mi)
#pragma unroll
        for (int nj = 0; nj < 4; ++nj) {
            int r0 = wm * 64 + mi * 16 + (lane >> 2);
            int cc = wn * 32 + nj * 8 + (lane & 3) * 2;
            stg[r0 * 132 + cc]           = acc[mi][nj][0];
            stg[r0 * 132 + cc + 1]       = acc[mi][nj][1];
            stg[(r0 + 8) * 132 + cc]     = acc[mi][nj][2];
            stg[(r0 + 8) * 132 + cc + 1] = acc[mi][nj][3];
        }
    __syncthreads();

    if (EPI == 2) {
#pragma unroll 4
        for (int it = 0; it < 32; ++it) {
            int e = it * 512 + tid * 2;
            int r = e >> 7, cc = e & 127;
            *(float2*)&fOut[(size_t)b * oBatch + (size_t)(mBase + r) * oStr + nBase + cc] =
                make_float2(stg[r * 132 + cc], stg[r * 132 + cc + 1]);
        }
    } else if (EPI == 0) {
#pragma unroll 4
        for (int it = 0; it < 32; ++it) {
            int e = it * 512 + tid * 2;
            int r = e >> 7, tc = e & 127;
            int d = mBase + r, t = nBase + tc;
            float2 g2 = *(const float2*)&g[((size_t)b * NC + d) * NT + t];
            float bb = bias[d];
            float v0 = g2.x * (stg[r * 132 + tc] + bb);
            float v1 = g2.y * (stg[r * 132 + tc + 1] + bb);
            __nv_bfloat16 h0, l0, h1, l1;
            split2(v0, h0, l0); split2(v1, h1, l1);
            size_t o = ((size_t)b * NC + d) * NT + t;
            *(uint32_t*)(oHi + o) = pack_bf2(h0, h1);
            *(uint32_t*)(oLo + o) = pack_bf2(l0, l1);
        }
    } else {
        // EPI 1 (v): pass 1 gate in [d][t]; pass 2 transposed write vT[b,t,d]
#pragma unroll 4
        for (int it = 0; it < 32; ++it) {
            int e = it * 512 + tid * 2;
            int r = e >> 7, tc = e & 127;
            int d = mBase + r, t = nBase + tc;
            float2 g2 = *(const float2*)&g[((size_t)b * NC + d) * NT + t];
            float bb = bias[d];
            stg[r * 132 + tc]     = g2.x * (stg[r * 132 + tc] + bb);
            stg[r * 132 + tc + 1] = g2.y * (stg[r * 132 + tc + 1] + bb);
        }
        __syncthreads();
#pragma unroll 4
        for (int it = 0; it < 32; ++it) {
            int e = it * 512 + tid * 2;
            int tr = e >> 7, dc = e & 127;
            float v0 = stg[dc * 132 + tr];
            float v1 = stg[(dc + 1) * 132 + tr];
            __nv_bfloat16 h0, l0, h1, l1;
            split2(v0, h0, l0); split2(v1, h1, l1);
            size_t o = ((size_t)b * NT + nBase + tr) * NC + mBase + dc;
            *(uint32_t*)(oHi + o) = pack_bf2(h0, h1);
            *(uint32_t*)(oLo + o) = pack_bf2(l0, l1);
        }
    }
}

// ---------------------------------------------------------------------------
// Softmax over rows of e, emit split bf16 attn planes
// ---------------------------------------------------------------------------
__global__ __launch_bounds__(128) void softmax_split(
    const float* __restrict__ e,
    __nv_bfloat16* __restrict__ aHi, __nv_bfloat16* __restrict__ aLo)
{
    const size_t row = blockIdx.x;
    const float* p = e + row * NC;
    const int tid = threadIdx.x, lane = tid & 31, warp = tid >> 5;
    __shared__ float smax[4], ssum[4];

    float4 v = *(const float4*)&p[tid * 4];
    float sx = v.x * SCALE_F, sy = v.y * SCALE_F, sz = v.z * SCALE_F, sw = v.w * SCALE_F;

    float m = fmaxf(fmaxf(sx, sy), fmaxf(sz, sw));
#pragma unroll
    for (int o = 16; o > 0; o >>= 1) m = fmaxf(m, __shfl_xor_sync(0xffffffffu, m, o));
    if (lane == 0) smax[warp] = m;
    __syncthreads();
    m = fmaxf(fmaxf(smax[0], smax[1]), fmaxf(smax[2], smax[3]));

    float e0 = __expf(sx - m), e1 = __expf(sy - m), e2 = __expf(sz - m), e3 = __expf(sw - m);
    float s = e0 + e1 + e2 + e3;
#pragma unroll
    for (int o = 16; o > 0; o >>= 1) s += __shfl_xor_sync(0xffffffffu, s, o);
    if (lane == 0) ssum[warp] = s;
    __syncthreads();
    s = ssum[0] + ssum[1] + ssum[2] + ssum[3];
    float inv = 1.0f / s;

    float r0 = e0 * inv, r1 = e1 * inv, r2 = e2 * inv, r3 = e3 * inv;
    __nv_bfloat16 h0, l0, h1, l1, h2, l2, h3, l3;
    split2(r0, h0, l0); split2(r1, h1, l1); split2(r2, h2, l2); split2(r3, h3, l3);
    size_t o = row * NC + tid * 4;
    *(uint2*)(aHi + o) = make_uint2(pack_bf2(h0, h1), pack_bf2(h2, h3));
    *(uint2*)(aLo + o) = make_uint2(pack_bf2(l0, l1), pack_bf2(l2, l3));
}

// ---------------------------------------------------------------------------
extern "C" void kernel_launch(void* const* d_in, const int* in_sizes, int n_in,
                              void* d_out, int out_size)
{
    const float* x  = (const float*)d_in[0];
    const float* gq = (const float*)d_in[1];
    const float* gk = (const float*)d_in[2];
    const float* gv = (const float*)d_in[3];
    const float* Wq = (const float*)d_in[4];
    const float* bq = (const float*)d_in[5];
    const float* Wk = (const float*)d_in[6];
    const float* bk = (const float*)d_in[7];
    const float* Wv = (const float*)d_in[8];
    const float* bv = (const float*)d_in[9];
    float* out = (float*)d_out;

    __nv_bfloat16 *xThi, *xTlo, *qhi, *qlo, *khi, *klo, *vThi, *vTlo, *ahi, *alo, *Whi, *Wlo;
    float* e;
    cudaGetSymbolAddress((void**)&xThi, g_xThi);
    cudaGetSymbolAddress((void**)&xTlo, g_xTlo);
    cudaGetSymbolAddress((void**)&qhi,  g_qhi);
    cudaGetSymbolAddress((void**)&qlo,  g_qlo);
    cudaGetSymbolAddress((void**)&khi,  g_khi);
    cudaGetSymbolAddress((void**)&klo,  g_klo);
    cudaGetSymbolAddress((void**)&vThi, g_vThi);
    cudaGetSymbolAddress((void**)&vTlo, g_vTlo);
    cudaGetSymbolAddress((void**)&ahi,  g_ahi);
    cudaGetSymbolAddress((void**)&alo,  g_alo);
    cudaGetSymbolAddress((void**)&Whi,  g_Whi);
    cudaGetSymbolAddress((void**)&Wlo,  g_Wlo);
    cudaGetSymbolAddress((void**)&e,    g_e);

    cudaFuncSetAttribute(gemm_tc<0>, cudaFuncAttributeMaxDynamicSharedMemorySize, SMEM_DYN);
    cudaFuncSetAttribute(gemm_tc<1>, cudaFuncAttributeMaxDynamicSharedMemorySize, SMEM_DYN);
    cudaFuncSetAttribute(gemm_tc<2>, cudaFuncAttributeMaxDynamicSharedMemorySize, SMEM_DYN);

    // Prep: transpose+split x; split the three weight matrices
    dim3 gT(NT / 32, NC / 32, NB);
    transpose_split<<<gT, dim3(32, 8)>>>(x, xThi, xTlo);
    const int WN = NC * NC;                       // 262144
    split_kernel<<<WN / 1024, 256>>>(Wq, Whi,             Wlo);
    split_kernel<<<WN / 1024, 256>>>(Wk, Whi + WN,        Wlo + WN);
    split_kernel<<<WN / 1024, 256>>>(Wv, Whi + 2 * WN,    Wlo + 2 * WN);

    // QKV gated linears: M=d(4 tiles), N=t(8 tiles), K=c (8 chunks)
    dim3 gQKV(NT / 128, NC / 128, NB);
    gemm_tc<0><<<gQKV, 256, SMEM_DYN>>>(Whi, Wlo, xThi, xTlo,
        NC, NC, 0, (size_t)NT * NC, 8, gq, bq, nullptr, 0, 0, qhi, qlo);
    gemm_tc<0><<<gQKV, 256, SMEM_DYN>>>(Whi + WN, Wlo + WN, xThi, xTlo,
        NC, NC, 0, (size_t)NT * NC, 8, gk, bk, nullptr, 0, 0, khi, klo);
    gemm_tc<1><<<gQKV, 256, SMEM_DYN>>>(Whi + 2 * WN, Wlo + 2 * WN, xThi, xTlo,
        NC, NC, 0, (size_t)NT * NC, 8, gv, bv, nullptr, 0, 0, vThi, vTlo);

    // Energy: M=c(4), N=d(4), K=t (16 chunks) -> fp32 e
    dim3 gE(NC / 128, NC / 128, NB);
    gemm_tc<2><<<gE, 256, SMEM_DYN>>>(qhi, qlo, khi, klo,
        NT, NT, (size_t)NC * NT, (size_t)NC * NT, 16,
        nullptr, nullptr, e, NC, (size_t)NC * NC, nullptr, nullptr);

    softmax_split<<<NB * NC, 128>>>(e, ahi, alo);

    // Output: M=c(4), N=t(8), K=d (8 chunks) -> fp32 out
    dim3 gO(NT / 128, NC / 128, NB);
    gemm_tc<2><<<gO, 256, SMEM_DYN>>>(ahi, alo, vThi, vTlo,
        NC, NC, (size_t)NC * NC, (size_t)NT * NC, 8,
        nullptr, nullptr, out, NT, (size_t)NC * NT, nullptr, nullptr);
}